// round 4
// baseline (speedup 1.0000x reference)
#include <cuda_runtime.h>
#include <cuda_fp16.h>

#define MAXN 50000
#define MAXE 1600000
#define NBLK 256

// ---------------- scratch (device globals; no allocation) ----------------
__device__ __half2 g_hh[MAXN * 32];    // x @ W_gat, fp16 (row = 64 cols = 32 half2)
__device__ float   g_acc[MAXN * 64];   // x @ W_res + b_gat + b_res (fp32)
__device__ float   g_asrc[MAXN * 4];
__device__ float   g_adst[MAXN * 4];
__device__ int     g_cnt[MAXN];        // in-degree (self-cleaned by k_agg)
__device__ int     g_cur[MAXN];        // scatter cursors
__device__ int     g_off[MAXN];        // row starts
__device__ int     g_total;            // row-start bump counter (self-cleaned)
__device__ int     g_srcs[MAXE];       // CSR: src ids grouped by dst
__device__ float4  g_w4[MAXE];         // per-edge softmax weights (4 heads)

__device__ __forceinline__ float leaky(float v) { return v > 0.f ? v : 0.2f * v; }

__device__ __forceinline__ unsigned long long pack2(float v) {
    unsigned long long r;
    asm("mov.b64 %0, {%1, %1};" : "=l"(r) : "f"(v));
    return r;
}
__device__ __forceinline__ void fma2(unsigned long long& acc, unsigned long long a,
                                     unsigned long long b) {
    asm("fma.rn.f32x2 %0, %1, %2, %0;" : "+l"(acc) : "l"(a), "l"(b));
}
__device__ __forceinline__ float2 unpack2(unsigned long long v) {
    float2 r;
    asm("mov.b64 {%0, %1}, %2;" : "=f"(r.x), "=f"(r.y) : "l"(v));
    return r;
}

// ---------------------------------------------------------------------------
// K1: fused dual GEMM (f32x2 packed FMA) + degree histogram (overlapped REDs).
//   g_hh  = fp16(x @ Wg), attention logits a_src/a_dst
//   g_acc = x @ Wr + b_gat + b_res
// CTA: 64 nodes, 256 threads. c=tid&15 -> 4 cols; s=tid>>4 -> nodes s+16i.
// Smem: Wg[8192] | Wr[8192] | xs[64*132] floats = 97 KB.
// ---------------------------------------------------------------------------
__global__ void k_gemm(const float* __restrict__ x,
                       const float* __restrict__ Wg, const float* __restrict__ Wr,
                       const float* __restrict__ b0, const float* __restrict__ b1,
                       const float* __restrict__ att_s, const float* __restrict__ att_d,
                       const int* __restrict__ ei, int n, int E) {
    extern __shared__ float sm[];
    float* sWg = sm;                 // 8192
    float* sWr = sm + 8192;          // 8192
    float* xs  = sm + 16384;         // 64*132 = 8448
    int tid = threadIdx.x;

    // --- fire-and-forget degree histogram (overlaps with GEMM) ---
    {
        int stride = gridDim.x * NBLK;
        for (int i = blockIdx.x * NBLK + tid; i < E; i += stride)
            atomicAdd(&g_cnt[ei[E + i]], 1);
    }

    for (int i = tid; i < 8192; i += NBLK) { sWg[i] = Wg[i]; sWr[i] = Wr[i]; }
    int base = blockIdx.x * 64;
    const float4* x4 = (const float4*)x;
    for (int i = tid; i < 64 * 32; i += NBLK) {
        int node = i >> 5, kk = i & 31;
        float4 v = make_float4(0.f, 0.f, 0.f, 0.f);
        if (base + node < n) v = x4[(base + node) * 32 + kk];
        ((float4*)(xs + node * 132))[kk] = v;
    }
    __syncthreads();

    int c = tid & 15;          // col group: cols 4c..4c+3
    int s = tid >> 4;          // node slot: nodes s+16i
    const ulonglong2* wgp = (const ulonglong2*)sWg;   // 16 ull2 per k-row
    const ulonglong2* wrp = (const ulonglong2*)sWr;
    const float* xk = xs + s * 132;

    unsigned long long ag[4][2] = {}, ar[4][2] = {};
#pragma unroll 8
    for (int k = 0; k < 128; k++) {
        ulonglong2 wg = wgp[k * 16 + c];
        ulonglong2 wr = wrp[k * 16 + c];
#pragma unroll
        for (int i = 0; i < 4; i++) {
            unsigned long long xx = pack2(xk[i * 16 * 132 + k]);
            fma2(ag[i][0], wg.x, xx);
            fma2(ag[i][1], wg.y, xx);
            fma2(ar[i][0], wr.x, xx);
            fma2(ar[i][1], wr.y, xx);
        }
    }

    float4 bv0 = ((const float4*)b0)[c];
    float4 bv1 = ((const float4*)b1)[c];
    float4 as4 = ((const float4*)att_s)[c];
    float4 ad4 = ((const float4*)att_d)[c];

#pragma unroll
    for (int i = 0; i < 4; i++) {
        int node = base + s + 16 * i;
        float2 g01 = unpack2(ag[i][0]);
        float2 g23 = unpack2(ag[i][1]);
        float2 r01 = unpack2(ar[i][0]);
        float2 r23 = unpack2(ar[i][1]);

        float ps = g01.x * as4.x + g01.y * as4.y + g23.x * as4.z + g23.y * as4.w;
        float pd = g01.x * ad4.x + g01.y * ad4.y + g23.x * ad4.z + g23.y * ad4.w;
        // reduce within 4-lane head groups (head h = c>>2)
        ps += __shfl_xor_sync(0xffffffffu, ps, 1);
        pd += __shfl_xor_sync(0xffffffffu, pd, 1);
        ps += __shfl_xor_sync(0xffffffffu, ps, 2);
        pd += __shfl_xor_sync(0xffffffffu, pd, 2);

        if (node < n) {
            __half2 h0 = __floats2half2_rn(g01.x, g01.y);
            __half2 h1 = __floats2half2_rn(g23.x, g23.y);
            uint2 hv = make_uint2(*(unsigned*)&h0, *(unsigned*)&h1);
            ((uint2*)g_hh)[node * 16 + c] = hv;
            ((float4*)g_acc)[node * 16 + c] =
                make_float4(r01.x + bv0.x + bv1.x, r01.y + bv0.y + bv1.y,
                            r23.x + bv0.z + bv1.z, r23.y + bv0.w + bv1.w);
            if ((c & 3) == 0) {
                g_asrc[node * 4 + (c >> 2)] = ps;
                g_adst[node * 4 + (c >> 2)] = pd;
            }
        }
    }
}

// ---------------------------------------------------------------------------
// K2: row starts via warp-aggregated bump allocation (rows need not be
// dst-ordered, only contiguous).
// ---------------------------------------------------------------------------
__global__ void k_rows(int n) {
    int i = blockIdx.x * NBLK + threadIdx.x;
    int lane = threadIdx.x & 31;
    int v = (i < n) ? g_cnt[i] : 0;
    int sc = v;
#pragma unroll
    for (int off = 1; off < 32; off <<= 1) {
        int t = __shfl_up_sync(0xffffffffu, sc, off);
        if (lane >= off) sc += t;
    }
    int tot = __shfl_sync(0xffffffffu, sc, 31);
    int rb = 0;
    if (lane == 31) rb = atomicAdd(&g_total, tot);
    rb = __shfl_sync(0xffffffffu, rb, 31);
    if (i < n) {
        int st = rb + sc - v;
        g_off[i] = st;
        g_cur[i] = st;
    }
}

// ---------------------------------------------------------------------------
// K3: scatter src ids into CSR order + precompute per-edge head weights
// ---------------------------------------------------------------------------
__global__ void k_scatter(const int* __restrict__ ei, int E) {
    int i = blockIdx.x * NBLK + threadIdx.x;
    if (i >= E) return;
    int s = ei[i], d = ei[E + i];
    int p = atomicAdd(&g_cur[d], 1);
    float4 as = ((const float4*)g_asrc)[s];
    float4 ad = ((const float4*)g_adst)[d];
    g_srcs[p] = s;
    g_w4[p] = make_float4(__expf(leaky(as.x + ad.x)),
                          __expf(leaky(as.y + ad.y)),
                          __expf(leaky(as.z + ad.z)),
                          __expf(leaky(as.w + ad.w)));
}

// ---------------------------------------------------------------------------
// K4: warp-per-destination gather aggregation (fp16 h), fused with residual +
// BN + ReLU + classifier. Self-cleans g_cnt/g_total for the next launch.
// Lane owns cols 2l,2l+1 (half2 #l); head hd = l>>3.
// ---------------------------------------------------------------------------
__global__ void k_agg(const float* __restrict__ gamma, const float* __restrict__ beta,
                      const float* __restrict__ rmean, const float* __restrict__ rvar,
                      const float* __restrict__ Wc, const float* __restrict__ bc,
                      float* __restrict__ out, int n) {
    __shared__ float sW[640], sS[64], sB[64], sbc[16];
    int tid = threadIdx.x;
    if (blockIdx.x == 0 && tid == 0) g_total = 0;
    for (int i = tid; i < 640; i += NBLK) sW[i] = Wc[i];
    if (tid < 64) {
        float sc = gamma[tid] * rsqrtf(rvar[tid] + 1e-5f);
        sS[tid] = sc;
        sB[tid] = beta[tid] - rmean[tid] * sc;
    }
    if (tid < 10) sbc[tid] = bc[tid];
    __syncthreads();

    int wid = tid >> 5, lane = tid & 31;
    int d = blockIdx.x * 8 + wid;
    if (d >= n) return;

    int hd = lane >> 3;
    int start = g_off[d];
    int deg = g_cnt[d];
    if (lane == 0) g_cnt[d] = 0;      // self-clean for next launch
    const float* wp = (const float*)g_w4;
    const unsigned* hp = (const unsigned*)g_hh;

    float m0 = 0.f, m1 = 0.f, den = 0.f;
    int p = start, rem = deg;
    for (; rem >= 4; rem -= 4, p += 4) {
        int s0 = g_srcs[p], s1 = g_srcs[p + 1], s2 = g_srcs[p + 2], s3 = g_srcs[p + 3];
        float w0 = wp[(p + 0) * 4 + hd];
        float w1 = wp[(p + 1) * 4 + hd];
        float w2 = wp[(p + 2) * 4 + hd];
        float w3 = wp[(p + 3) * 4 + hd];
        unsigned u0 = hp[s0 * 32 + lane];
        unsigned u1 = hp[s1 * 32 + lane];
        unsigned u2 = hp[s2 * 32 + lane];
        unsigned u3 = hp[s3 * 32 + lane];
        float2 h0 = __half22float2(*(__half2*)&u0);
        float2 h1 = __half22float2(*(__half2*)&u1);
        float2 h2 = __half22float2(*(__half2*)&u2);
        float2 h3 = __half22float2(*(__half2*)&u3);
        m0 += w0 * h0.x + w1 * h1.x;  m1 += w0 * h0.y + w1 * h1.y;
        m0 += w2 * h2.x + w3 * h3.x;  m1 += w2 * h2.y + w3 * h3.y;
        den += (w0 + w1) + (w2 + w3);
    }
    for (; rem > 0; rem--, p++) {
        int s = g_srcs[p];
        float w = wp[p * 4 + hd];
        unsigned u = hp[s * 32 + lane];
        float2 hv = __half22float2(*(__half2*)&u);
        m0 += w * hv.x; m1 += w * hv.y; den += w;
    }
    {   // self-loop
        float w = __expf(leaky(g_asrc[d * 4 + hd] + g_adst[d * 4 + hd]));
        unsigned u = hp[d * 32 + lane];
        float2 hv = __half22float2(*(__half2*)&u);
        m0 += w * hv.x; m1 += w * hv.y; den += w;
    }

    float inv = 1.f / (den + 1e-16f);
    float2 r = ((const float2*)g_acc)[d * 32 + lane];
    int c0 = 2 * lane;
    float h0 = r.x + m0 * inv;
    float h1 = r.y + m1 * inv;
    float hb0 = fmaxf(h0 * sS[c0] + sB[c0], 0.f);
    float hb1 = fmaxf(h1 * sS[c0 + 1] + sB[c0 + 1], 0.f);

    float lg[10];
#pragma unroll
    for (int cc = 0; cc < 10; cc++)
        lg[cc] = hb0 * sW[c0 * 10 + cc] + hb1 * sW[(c0 + 1) * 10 + cc];
#pragma unroll
    for (int off = 16; off; off >>= 1)
#pragma unroll
        for (int cc = 0; cc < 10; cc++)
            lg[cc] += __shfl_down_sync(0xffffffffu, lg[cc], off);
    if (lane == 0) {
#pragma unroll
        for (int cc = 0; cc < 10; cc++) out[d * 10 + cc] = lg[cc] + sbc[cc];
    }
}

extern "C" void kernel_launch(void* const* d_in, const int* in_sizes, int n_in,
                              void* d_out, int out_size) {
    const float* x     = (const float*)d_in[0];
    const int*   ei    = (const int*)d_in[1];
    const float* Wg    = (const float*)d_in[2];
    const float* att_s = (const float*)d_in[3];
    const float* att_d = (const float*)d_in[4];
    const float* bg    = (const float*)d_in[5];
    const float* Wr    = (const float*)d_in[6];
    const float* br    = (const float*)d_in[7];
    const float* gamma = (const float*)d_in[8];
    const float* beta  = (const float*)d_in[9];
    const float* rmean = (const float*)d_in[10];
    const float* rvar  = (const float*)d_in[11];
    const float* Wc    = (const float*)d_in[12];
    const float* bc    = (const float*)d_in[13];
    float* out = (float*)d_out;

    int n = in_sizes[0] / 128;
    int E = in_sizes[1] / 2;

    int nodeB = (n + NBLK - 1) / NBLK;
    int edgeB = (E + NBLK - 1) / NBLK;
    int gemmB = (n + 63) / 64;
    const int GEMM_SMEM = (8192 + 8192 + 64 * 132) * 4;   // 99328 B

    static int smem_set = 0;
    if (!smem_set) {
        cudaFuncSetAttribute(k_gemm, cudaFuncAttributeMaxDynamicSharedMemorySize, GEMM_SMEM);
        smem_set = 1;
    }

    k_gemm<<<gemmB, NBLK, GEMM_SMEM>>>(x, Wg, Wr, bg, br, att_s, att_d, ei, n, E);
    k_rows<<<nodeB, NBLK>>>(n);
    k_scatter<<<edgeB, NBLK>>>(ei, E);
    k_agg<<<(n + 7) / 8, NBLK>>>(gamma, beta, rmean, rvar, Wc, bc, out, n);
}

// round 5
// speedup vs baseline: 1.0088x; 1.0088x over previous
#include <cuda_runtime.h>

#define MAXN 50000
#define MAXE 1600000
#define MAXEP (MAXE + 3 * MAXN)   // padded CSR capacity (rows rounded to 4)
#define NBLK 256

// ---------------- scratch (device globals; no allocation) ----------------
__device__ float  g_h[MAXN * 64];      // x @ W_gat (fp32)
__device__ float  g_acc[MAXN * 64];    // x @ W_res + b_gat + b_res
__device__ float  g_asrc[MAXN * 4];
__device__ float  g_adst[MAXN * 4];
__device__ int    g_cnt[MAXN];         // in-degree (self-cleaned by k_agg)
__device__ int    g_cur[MAXN];         // scatter cursors
__device__ int    g_off[MAXN];         // row starts (4-aligned)
__device__ int    g_total;             // bump counter (self-cleaned by k_agg)
__device__ int    g_srcs[MAXEP];       // CSR src ids (+ zero pads)
__device__ float4 g_w4[MAXEP];         // per-edge head weights (+ zero pads)

__device__ __forceinline__ float leaky(float v) { return v > 0.f ? v : 0.2f * v; }

// ---------------------------------------------------------------------------
// K1: fused dual GEMM: g_h = x@Wg (+ attention logits), g_acc = x@Wr + biases.
// Dynamic smem: Wg[8192] | Wr[8192] | xs[32*128] floats = 80KB. (proven R3 code)
// ---------------------------------------------------------------------------
__global__ void k_gemm(const float* __restrict__ x,
                       const float* __restrict__ Wg, const float* __restrict__ Wr,
                       const float* __restrict__ b0, const float* __restrict__ b1,
                       const float* __restrict__ att_s, const float* __restrict__ att_d,
                       int n) {
    extern __shared__ float sm[];
    float* sWg = sm;
    float* sWr = sm + 8192;
    float* xs  = sm + 16384;
    int tid = threadIdx.x;
    for (int i = tid; i < 8192; i += NBLK) { sWg[i] = Wg[i]; sWr[i] = Wr[i]; }
    int base = blockIdx.x * 32;
    const float4* x4 = (const float4*)x;
    for (int i = tid; i < 32 * 32; i += NBLK) {
        int node = i >> 5, kk = i & 31;
        float4 v = make_float4(0.f, 0.f, 0.f, 0.f);
        if (base + node < n) v = x4[(base + node) * 32 + kk];
        ((float4*)xs)[i] = v;
    }
    __syncthreads();

    int tx = tid & 31;
    int ty = tid >> 5;
    float ag[4][2] = {}, ar[4][2] = {};
    const float* xp = xs + ty * 4 * 128;
#pragma unroll 4
    for (int k = 0; k < 128; k++) {
        float2 wg = ((const float2*)(sWg + k * 64))[tx];
        float2 wr = ((const float2*)(sWr + k * 64))[tx];
#pragma unroll
        for (int i = 0; i < 4; i++) {
            float xv = xp[i * 128 + k];
            ag[i][0] += xv * wg.x; ag[i][1] += xv * wg.y;
            ar[i][0] += xv * wr.x; ar[i][1] += xv * wr.y;
        }
    }

    float bias0 = b0[2 * tx] + b1[2 * tx];
    float bias1 = b0[2 * tx + 1] + b1[2 * tx + 1];
    float as0 = att_s[2 * tx], as1 = att_s[2 * tx + 1];
    float ad0 = att_d[2 * tx], ad1 = att_d[2 * tx + 1];
    int hd = tx >> 3;
#pragma unroll
    for (int i = 0; i < 4; i++) {
        int node = base + ty * 4 + i;
        float ps = ag[i][0] * as0 + ag[i][1] * as1;
        float pd = ag[i][0] * ad0 + ag[i][1] * ad1;
#pragma unroll
        for (int off = 4; off; off >>= 1) {
            ps += __shfl_xor_sync(0xffffffffu, ps, off);
            pd += __shfl_xor_sync(0xffffffffu, pd, off);
        }
        if (node < n) {
            ((float2*)(g_h + node * 64))[tx]   = make_float2(ag[i][0], ag[i][1]);
            ((float2*)(g_acc + node * 64))[tx] = make_float2(ar[i][0] + bias0, ar[i][1] + bias1);
            if ((tx & 7) == 0) {
                g_asrc[node * 4 + hd] = ps;
                g_adst[node * 4 + hd] = pd;
            }
        }
    }
}

// ---------------------------------------------------------------------------
// K2: degree histogram (int4)
// ---------------------------------------------------------------------------
__global__ void k_hist(const int* __restrict__ ei, int E) {
    int i = (blockIdx.x * NBLK + threadIdx.x) * 4;
    if (i + 3 < E) {
        int4 d = *(const int4*)(ei + E + i);
        atomicAdd(&g_cnt[d.x], 1);
        atomicAdd(&g_cnt[d.y], 1);
        atomicAdd(&g_cnt[d.z], 1);
        atomicAdd(&g_cnt[d.w], 1);
    } else {
        for (int j = i; j < E; j++) atomicAdd(&g_cnt[ei[E + j]], 1);
    }
}

// ---------------------------------------------------------------------------
// K3: row starts via warp-aggregated bump alloc; rows padded to multiple of 4
// (pads written as src=0 / w4=0 so they contribute nothing).
// ---------------------------------------------------------------------------
__global__ void k_rows(int n) {
    int i = blockIdx.x * NBLK + threadIdx.x;
    int lane = threadIdx.x & 31;
    int deg = (i < n) ? g_cnt[i] : 0;
    int sz = (deg + 3) & ~3;
    int sc = sz;
#pragma unroll
    for (int off = 1; off < 32; off <<= 1) {
        int t = __shfl_up_sync(0xffffffffu, sc, off);
        if (lane >= off) sc += t;
    }
    int tot = __shfl_sync(0xffffffffu, sc, 31);
    int rb = 0;
    if (lane == 31) rb = atomicAdd(&g_total, tot);
    rb = __shfl_sync(0xffffffffu, rb, 31);
    if (i < n) {
        int st = rb + sc - sz;
        g_off[i] = st;
        g_cur[i] = st;
        for (int j = deg; j < sz; j++) {
            g_srcs[st + j] = 0;
            g_w4[st + j] = make_float4(0.f, 0.f, 0.f, 0.f);
        }
    }
}

// ---------------------------------------------------------------------------
// K4: scatter src ids + per-edge head weights (2 edges/thread)
// ---------------------------------------------------------------------------
__global__ void k_scatter(const int* __restrict__ ei, int E) {
    int i = (blockIdx.x * NBLK + threadIdx.x) * 2;
    if (i >= E) return;
    int nn = min(2, E - i);
    for (int j = 0; j < nn; j++) {
        int s = ei[i + j], d = ei[E + i + j];
        int p = atomicAdd(&g_cur[d], 1);
        float4 as = ((const float4*)g_asrc)[s];
        float4 ad = ((const float4*)g_adst)[d];
        g_srcs[p] = s;
        g_w4[p] = make_float4(__expf(leaky(as.x + ad.x)),
                              __expf(leaky(as.y + ad.y)),
                              __expf(leaky(as.z + ad.z)),
                              __expf(leaky(as.w + ad.w)));
    }
}

// ---------------------------------------------------------------------------
// K5: warp-per-destination gather aggregation, 8-edge blocks (int4 src loads,
// immediate-offset w loads, 8 gathers in flight), fused epilogue.
// Lane owns cols 2l,2l+1; head hd = l>>3. Self-cleans g_cnt/g_total.
// ---------------------------------------------------------------------------
__global__ void __launch_bounds__(NBLK) k_agg(
        const float* __restrict__ gamma, const float* __restrict__ beta,
        const float* __restrict__ rmean, const float* __restrict__ rvar,
        const float* __restrict__ Wc, const float* __restrict__ bc,
        float* __restrict__ out, int n) {
    __shared__ float sW[640], sS[64], sB[64], sbc[16];
    int tid = threadIdx.x;
    if (blockIdx.x == 0 && tid == 0) g_total = 0;
    for (int i = tid; i < 640; i += NBLK) sW[i] = Wc[i];
    if (tid < 64) {
        float sc = gamma[tid] * rsqrtf(rvar[tid] + 1e-5f);
        sS[tid] = sc;
        sB[tid] = beta[tid] - rmean[tid] * sc;
    }
    if (tid < 10) sbc[tid] = bc[tid];
    __syncthreads();

    int wid = tid >> 5, lane = tid & 31;
    int d = blockIdx.x * 8 + wid;
    if (d >= n) return;

    int hd = lane >> 3;
    int start = g_off[d];
    int deg = g_cnt[d];
    if (lane == 0) g_cnt[d] = 0;
    const int*    sp = g_srcs + start;
    const float*  wp = (const float*)g_w4 + (long long)start * 4 + hd;
    const float2* hp = (const float2*)g_h;

    float m0 = 0.f, m1 = 0.f, den = 0.f;
    int dp = (deg + 3) & ~3;
    int k = 0;
    for (; k + 8 <= dp; k += 8) {
        int4 a = *(const int4*)(sp + k);
        int4 b = *(const int4*)(sp + k + 4);
        float w0 = wp[4 * k];      float w1 = wp[4 * k + 4];
        float w2 = wp[4 * k + 8];  float w3 = wp[4 * k + 12];
        float w4 = wp[4 * k + 16]; float w5 = wp[4 * k + 20];
        float w6 = wp[4 * k + 24]; float w7 = wp[4 * k + 28];
        float2 h0 = hp[a.x * 32 + lane];
        float2 h1 = hp[a.y * 32 + lane];
        float2 h2 = hp[a.z * 32 + lane];
        float2 h3 = hp[a.w * 32 + lane];
        float2 h4 = hp[b.x * 32 + lane];
        float2 h5 = hp[b.y * 32 + lane];
        float2 h6 = hp[b.z * 32 + lane];
        float2 h7 = hp[b.w * 32 + lane];
        m0 += w0 * h0.x + w1 * h1.x + w2 * h2.x + w3 * h3.x;
        m1 += w0 * h0.y + w1 * h1.y + w2 * h2.y + w3 * h3.y;
        m0 += w4 * h4.x + w5 * h5.x + w6 * h6.x + w7 * h7.x;
        m1 += w4 * h4.y + w5 * h5.y + w6 * h6.y + w7 * h7.y;
        den += ((w0 + w1) + (w2 + w3)) + ((w4 + w5) + (w6 + w7));
    }
    if (k < dp) {   // remainder is exactly one 4-block
        int4 a = *(const int4*)(sp + k);
        float w0 = wp[4 * k];      float w1 = wp[4 * k + 4];
        float w2 = wp[4 * k + 8];  float w3 = wp[4 * k + 12];
        float2 h0 = hp[a.x * 32 + lane];
        float2 h1 = hp[a.y * 32 + lane];
        float2 h2 = hp[a.z * 32 + lane];
        float2 h3 = hp[a.w * 32 + lane];
        m0 += w0 * h0.x + w1 * h1.x + w2 * h2.x + w3 * h3.x;
        m1 += w0 * h0.y + w1 * h1.y + w2 * h2.y + w3 * h3.y;
        den += (w0 + w1) + (w2 + w3);
    }
    {   // self-loop
        float w = __expf(leaky(g_asrc[d * 4 + hd] + g_adst[d * 4 + hd]));
        float2 hv = hp[d * 32 + lane];
        m0 += w * hv.x; m1 += w * hv.y; den += w;
    }

    float inv = 1.f / (den + 1e-16f);
    float2 r = ((const float2*)g_acc)[d * 32 + lane];
    int c0 = 2 * lane;
    float h0 = r.x + m0 * inv;
    float h1 = r.y + m1 * inv;
    float hb0 = fmaxf(h0 * sS[c0] + sB[c0], 0.f);
    float hb1 = fmaxf(h1 * sS[c0 + 1] + sB[c0 + 1], 0.f);

    float lg[10];
#pragma unroll
    for (int cc = 0; cc < 10; cc++)
        lg[cc] = hb0 * sW[c0 * 10 + cc] + hb1 * sW[(c0 + 1) * 10 + cc];
#pragma unroll
    for (int off = 16; off; off >>= 1)
#pragma unroll
        for (int cc = 0; cc < 10; cc++)
            lg[cc] += __shfl_down_sync(0xffffffffu, lg[cc], off);
    if (lane == 0) {
#pragma unroll
        for (int cc = 0; cc < 10; cc++) out[d * 10 + cc] = lg[cc] + sbc[cc];
    }
}

extern "C" void kernel_launch(void* const* d_in, const int* in_sizes, int n_in,
                              void* d_out, int out_size) {
    const float* x     = (const float*)d_in[0];
    const int*   ei    = (const int*)d_in[1];
    const float* Wg    = (const float*)d_in[2];
    const float* att_s = (const float*)d_in[3];
    const float* att_d = (const float*)d_in[4];
    const float* bg    = (const float*)d_in[5];
    const float* Wr    = (const float*)d_in[6];
    const float* br    = (const float*)d_in[7];
    const float* gamma = (const float*)d_in[8];
    const float* beta  = (const float*)d_in[9];
    const float* rmean = (const float*)d_in[10];
    const float* rvar  = (const float*)d_in[11];
    const float* Wc    = (const float*)d_in[12];
    const float* bc    = (const float*)d_in[13];
    float* out = (float*)d_out;

    int n = in_sizes[0] / 128;
    int E = in_sizes[1] / 2;

    int nodeB = (n + NBLK - 1) / NBLK;
    int gemmB = (n + 31) / 32;

    static cudaStream_t s2 = nullptr;
    static cudaEvent_t evFork = nullptr, evJoin = nullptr;
    static int smem_set = 0;
    if (!smem_set) {
        cudaFuncSetAttribute(k_gemm, cudaFuncAttributeMaxDynamicSharedMemorySize, 81920);
        cudaStreamCreateWithFlags(&s2, cudaStreamNonBlocking);
        cudaEventCreateWithFlags(&evFork, cudaEventDisableTiming);
        cudaEventCreateWithFlags(&evJoin, cudaEventDisableTiming);
        smem_set = 1;
    }

    // fork: CSR build (hist + rows) runs concurrently with the GEMM
    cudaEventRecord(evFork, 0);
    cudaStreamWaitEvent(s2, evFork, 0);

    k_gemm<<<gemmB, NBLK, 81920>>>(x, Wg, Wr, bg, br, att_s, att_d, n);

    k_hist<<<(E / 4 + NBLK - 1) / NBLK, NBLK, 0, s2>>>(ei, E);
    k_rows<<<nodeB, NBLK, 0, s2>>>(n);
    cudaEventRecord(evJoin, s2);
    cudaStreamWaitEvent(0, evJoin, 0);

    k_scatter<<<(E / 2 + NBLK - 1) / NBLK, NBLK>>>(ei, E);
    k_agg<<<(n + 7) / 8, NBLK>>>(gamma, beta, rmean, rvar, Wc, bc, out, n);
}

// round 6
// speedup vs baseline: 1.0811x; 1.0716x over previous
#include <cuda_runtime.h>

#define MAXN 50000
#define MAXE 1600000
#define MAXEP (MAXE + 3 * MAXN)   // padded CSR capacity (rows rounded to 4)
#define NBLK 256

// ---------------- scratch (device globals; no allocation) ----------------
__device__ float  g_h[MAXN * 64];      // x @ W_gat (fp32)
__device__ float  g_acc[MAXN * 64];    // x @ W_res + b_gat + b_res
__device__ float  g_asrc[MAXN * 4];
__device__ float  g_adst[MAXN * 4];
__device__ int    g_cnt[MAXN];         // in-degree (self-cleaned by k_agg)
__device__ int    g_off[MAXN];         // row starts (4-aligned)
__device__ int    g_total;             // bump counter (self-cleaned by k_agg)
__device__ int    g_rank[MAXE];        // per-edge within-dst rank (from k_hist)
__device__ int    g_srcs[MAXEP];       // CSR src ids (+ zero pads)
__device__ float4 g_w4[MAXEP];         // per-edge head weights (+ zero pads)

__device__ __forceinline__ float leaky(float v) { return v > 0.f ? v : 0.2f * v; }

// ---------------------------------------------------------------------------
// K1: fused dual GEMM: g_h = x@Wg (+ attention logits), g_acc = x@Wr + biases.
// Dynamic smem: Wg[8192] | Wr[8192] | xs[32*128] floats = 80KB. (proven)
// ---------------------------------------------------------------------------
__global__ void k_gemm(const float* __restrict__ x,
                       const float* __restrict__ Wg, const float* __restrict__ Wr,
                       const float* __restrict__ b0, const float* __restrict__ b1,
                       const float* __restrict__ att_s, const float* __restrict__ att_d,
                       int n) {
    extern __shared__ float sm[];
    float* sWg = sm;
    float* sWr = sm + 8192;
    float* xs  = sm + 16384;
    int tid = threadIdx.x;
    for (int i = tid; i < 8192; i += NBLK) { sWg[i] = Wg[i]; sWr[i] = Wr[i]; }
    int base = blockIdx.x * 32;
    const float4* x4 = (const float4*)x;
    for (int i = tid; i < 32 * 32; i += NBLK) {
        int node = i >> 5, kk = i & 31;
        float4 v = make_float4(0.f, 0.f, 0.f, 0.f);
        if (base + node < n) v = x4[(base + node) * 32 + kk];
        ((float4*)xs)[i] = v;
    }
    __syncthreads();

    int tx = tid & 31;
    int ty = tid >> 5;
    float ag[4][2] = {}, ar[4][2] = {};
    const float* xp = xs + ty * 4 * 128;
#pragma unroll 4
    for (int k = 0; k < 128; k++) {
        float2 wg = ((const float2*)(sWg + k * 64))[tx];
        float2 wr = ((const float2*)(sWr + k * 64))[tx];
#pragma unroll
        for (int i = 0; i < 4; i++) {
            float xv = xp[i * 128 + k];
            ag[i][0] += xv * wg.x; ag[i][1] += xv * wg.y;
            ar[i][0] += xv * wr.x; ar[i][1] += xv * wr.y;
        }
    }

    float bias0 = b0[2 * tx] + b1[2 * tx];
    float bias1 = b0[2 * tx + 1] + b1[2 * tx + 1];
    float as0 = att_s[2 * tx], as1 = att_s[2 * tx + 1];
    float ad0 = att_d[2 * tx], ad1 = att_d[2 * tx + 1];
    int hd = tx >> 3;
#pragma unroll
    for (int i = 0; i < 4; i++) {
        int node = base + ty * 4 + i;
        float ps = ag[i][0] * as0 + ag[i][1] * as1;
        float pd = ag[i][0] * ad0 + ag[i][1] * ad1;
#pragma unroll
        for (int off = 4; off; off >>= 1) {
            ps += __shfl_xor_sync(0xffffffffu, ps, off);
            pd += __shfl_xor_sync(0xffffffffu, pd, off);
        }
        if (node < n) {
            ((float2*)(g_h + node * 64))[tx]   = make_float2(ag[i][0], ag[i][1]);
            ((float2*)(g_acc + node * 64))[tx] = make_float2(ar[i][0] + bias0, ar[i][1] + bias1);
            if ((tx & 7) == 0) {
                g_asrc[node * 4 + hd] = ps;
                g_adst[node * 4 + hd] = pd;
            }
        }
    }
}

// ---------------------------------------------------------------------------
// K2: degree histogram + per-edge rank capture (runs under the GEMM)
// ---------------------------------------------------------------------------
__global__ void k_hist(const int* __restrict__ ei, int E) {
    int i = blockIdx.x * NBLK + threadIdx.x;
    if (i < E) g_rank[i] = atomicAdd(&g_cnt[ei[E + i]], 1);
}

// ---------------------------------------------------------------------------
// K3: row starts via warp-aggregated bump alloc; rows padded to multiple of 4
// (pads written with w4=0 so they contribute nothing).
// ---------------------------------------------------------------------------
__global__ void k_rows(int n) {
    int i = blockIdx.x * NBLK + threadIdx.x;
    int lane = threadIdx.x & 31;
    int deg = (i < n) ? g_cnt[i] : 0;
    int sz = (deg + 3) & ~3;
    int sc = sz;
#pragma unroll
    for (int off = 1; off < 32; off <<= 1) {
        int t = __shfl_up_sync(0xffffffffu, sc, off);
        if (lane >= off) sc += t;
    }
    int tot = __shfl_sync(0xffffffffu, sc, 31);
    int rb = 0;
    if (lane == 31) rb = atomicAdd(&g_total, tot);
    rb = __shfl_sync(0xffffffffu, rb, 31);
    if (i < n) {
        int st = rb + sc - sz;
        g_off[i] = st;
        for (int j = deg; j < sz; j++) {
            g_srcs[st + j] = 0;
            g_w4[st + j] = make_float4(0.f, 0.f, 0.f, 0.f);
        }
    }
}

// ---------------------------------------------------------------------------
// K4: atomic-free scatter (slot = row start + precomputed rank) + weights
// ---------------------------------------------------------------------------
__global__ void k_scatter(const int* __restrict__ ei, int E) {
    int i = blockIdx.x * NBLK + threadIdx.x;
    if (i >= E) return;
    int s = ei[i], d = ei[E + i];
    int p = g_off[d] + g_rank[i];
    float4 as = ((const float4*)g_asrc)[s];
    float4 ad = ((const float4*)g_adst)[d];
    g_srcs[p] = s;
    g_w4[p] = make_float4(__expf(leaky(as.x + ad.x)),
                          __expf(leaky(as.y + ad.y)),
                          __expf(leaky(as.z + ad.z)),
                          __expf(leaky(as.w + ad.w)));
}

// ---------------------------------------------------------------------------
// K5: warp-per-destination aggregation, 16 lanes per edge (float4/lane):
// lane = (sub = l>>4, colgroup c = l&15). One LDG.128 fetches 2 edges' rows.
// Cross-sub combine via shfl_xor 16. Fused residual+BN+ReLU+classifier.
// Self-cleans g_cnt / g_total.
// ---------------------------------------------------------------------------
__global__ void __launch_bounds__(NBLK) k_agg(
        const float* __restrict__ gamma, const float* __restrict__ beta,
        const float* __restrict__ rmean, const float* __restrict__ rvar,
        const float* __restrict__ Wc, const float* __restrict__ bc,
        float* __restrict__ out, int n) {
    __shared__ float sW[640], sS[64], sB[64], sbc[16];
    int tid = threadIdx.x;
    if (blockIdx.x == 0 && tid == 0) g_total = 0;
    for (int i = tid; i < 640; i += NBLK) sW[i] = Wc[i];
    if (tid < 64) {
        float sc = gamma[tid] * rsqrtf(rvar[tid] + 1e-5f);
        sS[tid] = sc;
        sB[tid] = beta[tid] - rmean[tid] * sc;
    }
    if (tid < 10) sbc[tid] = bc[tid];
    __syncthreads();

    int wid = tid >> 5, lane = tid & 31;
    int d = blockIdx.x * 8 + wid;
    if (d >= n) return;

    int sub = lane >> 4;        // which edge of the pair
    int c   = lane & 15;        // col group: cols 4c..4c+3
    int hd  = c >> 2;           // head of this col group
    int start = g_off[d];
    int deg = g_cnt[d];
    if (lane == 0) g_cnt[d] = 0;

    const int*    sp  = g_srcs + start;                       // 16B-aligned
    const float*  wp  = (const float*)g_w4 + start * 4 + sub * 4 + hd;
    const float4* hp4 = (const float4*)g_h;

    float4 m = make_float4(0.f, 0.f, 0.f, 0.f);
    float den = 0.f;
    int dp = (deg + 3) & ~3;
    int k = 0;
    for (; k + 8 <= dp; k += 8) {
        int4 a = *(const int4*)(sp + k);      // uniform: 8 srcs in regs
        int4 b = *(const int4*)(sp + k + 4);
        int s0 = sub ? a.y : a.x;
        int s1 = sub ? a.w : a.z;
        int s2 = sub ? b.y : b.x;
        int s3 = sub ? b.w : b.z;
        float w0 = wp[4 * k];
        float w1 = wp[4 * k + 8];
        float w2 = wp[4 * k + 16];
        float w3 = wp[4 * k + 24];
        float4 h0 = hp4[s0 * 16 + c];
        float4 h1 = hp4[s1 * 16 + c];
        float4 h2 = hp4[s2 * 16 + c];
        float4 h3 = hp4[s3 * 16 + c];
        m.x += w0 * h0.x + w1 * h1.x + w2 * h2.x + w3 * h3.x;
        m.y += w0 * h0.y + w1 * h1.y + w2 * h2.y + w3 * h3.y;
        m.z += w0 * h0.z + w1 * h1.z + w2 * h2.z + w3 * h3.z;
        m.w += w0 * h0.w + w1 * h1.w + w2 * h2.w + w3 * h3.w;
        den += (w0 + w1) + (w2 + w3);
    }
    if (k < dp) {   // remainder: exactly one 4-block (2 pairs)
        int4 a = *(const int4*)(sp + k);
        int s0 = sub ? a.y : a.x;
        int s1 = sub ? a.w : a.z;
        float w0 = wp[4 * k];
        float w1 = wp[4 * k + 8];
        float4 h0 = hp4[s0 * 16 + c];
        float4 h1 = hp4[s1 * 16 + c];
        m.x += w0 * h0.x + w1 * h1.x;
        m.y += w0 * h0.y + w1 * h1.y;
        m.z += w0 * h0.z + w1 * h1.z;
        m.w += w0 * h0.w + w1 * h1.w;
        den += w0 + w1;
    }

    // combine the two edge-subslots (lanes l and l^16 end identical)
    m.x += __shfl_xor_sync(0xffffffffu, m.x, 16);
    m.y += __shfl_xor_sync(0xffffffffu, m.y, 16);
    m.z += __shfl_xor_sync(0xffffffffu, m.z, 16);
    m.w += __shfl_xor_sync(0xffffffffu, m.w, 16);
    den += __shfl_xor_sync(0xffffffffu, den, 16);

    {   // self-loop (all lanes add identically)
        float w = __expf(leaky(g_asrc[d * 4 + hd] + g_adst[d * 4 + hd]));
        float4 hv = hp4[d * 16 + c];
        m.x += w * hv.x; m.y += w * hv.y; m.z += w * hv.z; m.w += w * hv.w;
        den += w;
    }

    float inv = 1.f / (den + 1e-16f);
    float4 r = ((const float4*)g_acc)[d * 16 + c];
    int c0 = 4 * c;
    float hb0 = fmaxf((r.x + m.x * inv) * sS[c0]     + sB[c0],     0.f);
    float hb1 = fmaxf((r.y + m.y * inv) * sS[c0 + 1] + sB[c0 + 1], 0.f);
    float hb2 = fmaxf((r.z + m.z * inv) * sS[c0 + 2] + sB[c0 + 2], 0.f);
    float hb3 = fmaxf((r.w + m.w * inv) * sS[c0 + 3] + sB[c0 + 3], 0.f);

    float lg[10];
#pragma unroll
    for (int cc = 0; cc < 10; cc++)
        lg[cc] = hb0 * sW[c0 * 10 + cc]        + hb1 * sW[(c0 + 1) * 10 + cc]
               + hb2 * sW[(c0 + 2) * 10 + cc]  + hb3 * sW[(c0 + 3) * 10 + cc];
    // reduce within 16-lane halves (lanes 0-15 cover all 16 col groups)
#pragma unroll
    for (int off = 8; off; off >>= 1)
#pragma unroll
        for (int cc = 0; cc < 10; cc++)
            lg[cc] += __shfl_xor_sync(0xffffffffu, lg[cc], off);
    if (lane == 0) {
#pragma unroll
        for (int cc = 0; cc < 10; cc++) out[d * 10 + cc] = lg[cc] + sbc[cc];
    }
}

extern "C" void kernel_launch(void* const* d_in, const int* in_sizes, int n_in,
                              void* d_out, int out_size) {
    const float* x     = (const float*)d_in[0];
    const int*   ei    = (const int*)d_in[1];
    const float* Wg    = (const float*)d_in[2];
    const float* att_s = (const float*)d_in[3];
    const float* att_d = (const float*)d_in[4];
    const float* bg    = (const float*)d_in[5];
    const float* Wr    = (const float*)d_in[6];
    const float* br    = (const float*)d_in[7];
    const float* gamma = (const float*)d_in[8];
    const float* beta  = (const float*)d_in[9];
    const float* rmean = (const float*)d_in[10];
    const float* rvar  = (const float*)d_in[11];
    const float* Wc    = (const float*)d_in[12];
    const float* bc    = (const float*)d_in[13];
    float* out = (float*)d_out;

    int n = in_sizes[0] / 128;
    int E = in_sizes[1] / 2;

    int nodeB = (n + NBLK - 1) / NBLK;
    int edgeB = (E + NBLK - 1) / NBLK;
    int gemmB = (n + 31) / 32;

    static cudaStream_t s2 = nullptr;
    static cudaEvent_t evFork = nullptr, evJoin = nullptr;
    static int init_done = 0;
    if (!init_done) {
        cudaFuncSetAttribute(k_gemm, cudaFuncAttributeMaxDynamicSharedMemorySize, 81920);
        cudaStreamCreateWithFlags(&s2, cudaStreamNonBlocking);
        cudaEventCreateWithFlags(&evFork, cudaEventDisableTiming);
        cudaEventCreateWithFlags(&evJoin, cudaEventDisableTiming);
        init_done = 1;
    }

    // fork: CSR build (hist + rows) runs concurrently with the GEMM
    cudaEventRecord(evFork, 0);
    cudaStreamWaitEvent(s2, evFork, 0);

    k_gemm<<<gemmB, NBLK, 81920>>>(x, Wg, Wr, bg, br, att_s, att_d, n);

    k_hist<<<edgeB, NBLK, 0, s2>>>(ei, E);
    k_rows<<<nodeB, NBLK, 0, s2>>>(n);
    cudaEventRecord(evJoin, s2);
    cudaStreamWaitEvent(0, evJoin, 0);

    k_scatter<<<edgeB, NBLK>>>(ei, E);
    k_agg<<<(n + 7) / 8, NBLK>>>(gamma, beta, rmean, rvar, Wc, bc, out, n);
}

// round 7
// speedup vs baseline: 1.1306x; 1.0458x over previous
#include <cuda_runtime.h>

#define MAXN 50000
#define MAXE 1600000
#define MAXEP (MAXE + 3 * MAXN)   // padded CSR capacity (rows rounded to 4)
#define NBLK 256

// ---------------- scratch (device globals; no allocation) ----------------
__device__ float  g_h[(MAXN + 1) * 64];   // x @ W_gat (row MAXN = sentinel, stays 0)
__device__ float  g_acc[MAXN * 64];       // x @ W_res + b_gat + b_res
__device__ float  g_asrc[(MAXN + 1) * 4]; // row MAXN = -1e30 sentinel (w -> 0)
__device__ float  g_adst[MAXN * 4];
__device__ int    g_cnt[MAXN];            // in-degree (self-cleaned by k_agg)
__device__ int    g_off[MAXN];            // row starts (4-aligned)
__device__ int    g_total;                // bump counter (self-cleaned by k_agg)
__device__ int    g_rank[MAXE];           // per-edge within-dst rank (from k_hist)
__device__ int    g_srcs[MAXEP];          // CSR src ids (+ sentinel pads)

__device__ __forceinline__ float leaky(float v) { return v > 0.f ? v : 0.2f * v; }

// ---------------------------------------------------------------------------
// K1: fused dual GEMM: g_h = x@Wg (+ attention logits), g_acc = x@Wr + biases.
// Dynamic smem: Wg[8192] | Wr[8192] | xs[32*128] floats = 80KB. (proven)
// ---------------------------------------------------------------------------
__global__ void k_gemm(const float* __restrict__ x,
                       const float* __restrict__ Wg, const float* __restrict__ Wr,
                       const float* __restrict__ b0, const float* __restrict__ b1,
                       const float* __restrict__ att_s, const float* __restrict__ att_d,
                       int n) {
    extern __shared__ float sm[];
    float* sWg = sm;
    float* sWr = sm + 8192;
    float* xs  = sm + 16384;
    int tid = threadIdx.x;
    for (int i = tid; i < 8192; i += NBLK) { sWg[i] = Wg[i]; sWr[i] = Wr[i]; }
    int base = blockIdx.x * 32;
    const float4* x4 = (const float4*)x;
    for (int i = tid; i < 32 * 32; i += NBLK) {
        int node = i >> 5, kk = i & 31;
        float4 v = make_float4(0.f, 0.f, 0.f, 0.f);
        if (base + node < n) v = x4[(base + node) * 32 + kk];
        ((float4*)xs)[i] = v;
    }
    __syncthreads();

    int tx = tid & 31;
    int ty = tid >> 5;
    float ag[4][2] = {}, ar[4][2] = {};
    const float* xp = xs + ty * 4 * 128;
#pragma unroll 4
    for (int k = 0; k < 128; k++) {
        float2 wg = ((const float2*)(sWg + k * 64))[tx];
        float2 wr = ((const float2*)(sWr + k * 64))[tx];
#pragma unroll
        for (int i = 0; i < 4; i++) {
            float xv = xp[i * 128 + k];
            ag[i][0] += xv * wg.x; ag[i][1] += xv * wg.y;
            ar[i][0] += xv * wr.x; ar[i][1] += xv * wr.y;
        }
    }

    float bias0 = b0[2 * tx] + b1[2 * tx];
    float bias1 = b0[2 * tx + 1] + b1[2 * tx + 1];
    float as0 = att_s[2 * tx], as1 = att_s[2 * tx + 1];
    float ad0 = att_d[2 * tx], ad1 = att_d[2 * tx + 1];
    int hd = tx >> 3;
#pragma unroll
    for (int i = 0; i < 4; i++) {
        int node = base + ty * 4 + i;
        float ps = ag[i][0] * as0 + ag[i][1] * as1;
        float pd = ag[i][0] * ad0 + ag[i][1] * ad1;
#pragma unroll
        for (int off = 4; off; off >>= 1) {
            ps += __shfl_xor_sync(0xffffffffu, ps, off);
            pd += __shfl_xor_sync(0xffffffffu, pd, off);
        }
        if (node < n) {
            ((float2*)(g_h + node * 64))[tx]   = make_float2(ag[i][0], ag[i][1]);
            ((float2*)(g_acc + node * 64))[tx] = make_float2(ar[i][0] + bias0, ar[i][1] + bias1);
            if ((tx & 7) == 0) {
                g_asrc[node * 4 + hd] = ps;
                g_adst[node * 4 + hd] = pd;
            }
        }
    }
}

// ---------------------------------------------------------------------------
// K2: degree histogram + per-edge rank capture (runs under the GEMM)
// ---------------------------------------------------------------------------
__global__ void k_hist(const int* __restrict__ ei, int E) {
    int i = blockIdx.x * NBLK + threadIdx.x;
    if (i < E) g_rank[i] = atomicAdd(&g_cnt[ei[E + i]], 1);
}

// ---------------------------------------------------------------------------
// K3: row starts via warp-aggregated bump alloc; rows padded to multiple of 4,
// pads get sentinel src = n (zero weight, zero h). Also writes the sentinel
// asrc row (constant -> deterministic).
// ---------------------------------------------------------------------------
__global__ void k_rows(int n) {
    int i = blockIdx.x * NBLK + threadIdx.x;
    int lane = threadIdx.x & 31;
    if (i < 4) g_asrc[n * 4 + i] = -1e30f;   // sentinel row: exp -> 0
    int deg = (i < n) ? g_cnt[i] : 0;
    int sz = (deg + 3) & ~3;
    int sc = sz;
#pragma unroll
    for (int off = 1; off < 32; off <<= 1) {
        int t = __shfl_up_sync(0xffffffffu, sc, off);
        if (lane >= off) sc += t;
    }
    int tot = __shfl_sync(0xffffffffu, sc, 31);
    int rb = 0;
    if (lane == 31) rb = atomicAdd(&g_total, tot);
    rb = __shfl_sync(0xffffffffu, rb, 31);
    if (i < n) {
        int st = rb + sc - sz;
        g_off[i] = st;
        for (int j = deg; j < sz; j++) g_srcs[st + j] = n;
    }
}

// ---------------------------------------------------------------------------
// K4: atomic-free scatter of src ids only (no GEMM dependency -> overlapped)
// ---------------------------------------------------------------------------
__global__ void k_scatter(const int* __restrict__ ei, int E) {
    int i = blockIdx.x * NBLK + threadIdx.x;
    if (i >= E) return;
    int s = ei[i], d = ei[E + i];
    g_srcs[g_off[d] + g_rank[i]] = s;
}

// ---------------------------------------------------------------------------
// K5: warp-per-destination aggregation, 16 lanes per edge (float4/lane),
// attention weights computed inline (broadcast asrc4 load + exp).
// Fused residual + BN + ReLU + classifier. Self-cleans g_cnt / g_total.
// ---------------------------------------------------------------------------
__global__ void __launch_bounds__(NBLK) k_agg(
        const float* __restrict__ gamma, const float* __restrict__ beta,
        const float* __restrict__ rmean, const float* __restrict__ rvar,
        const float* __restrict__ Wc, const float* __restrict__ bc,
        float* __restrict__ out, int n) {
    __shared__ float sW[640], sS[64], sB[64], sbc[16];
    int tid = threadIdx.x;
    if (blockIdx.x == 0 && tid == 0) g_total = 0;
    for (int i = tid; i < 640; i += NBLK) sW[i] = Wc[i];
    if (tid < 64) {
        float sc = gamma[tid] * rsqrtf(rvar[tid] + 1e-5f);
        sS[tid] = sc;
        sB[tid] = beta[tid] - rmean[tid] * sc;
    }
    if (tid < 10) sbc[tid] = bc[tid];
    __syncthreads();

    int wid = tid >> 5, lane = tid & 31;
    int d = blockIdx.x * 8 + wid;
    if (d >= n) return;

    int sub = lane >> 4;        // which edge of the pair
    int c   = lane & 15;        // col group: cols 4c..4c+3
    int hd  = c >> 2;           // head of this col group
    bool pb0 = hd & 1, pb1 = hd & 2;
    float adl = g_adst[d * 4 + hd];
    int start = g_off[d];
    int deg = g_cnt[d];
    if (lane == 0) g_cnt[d] = 0;

    const int*    sp  = g_srcs + start;            // 16B-aligned
    const float4* as4 = (const float4*)g_asrc;
    const float4* hp4 = (const float4*)g_h;

#define SELH(v) (pb1 ? (pb0 ? (v).w : (v).z) : (pb0 ? (v).y : (v).x))

    float4 m = make_float4(0.f, 0.f, 0.f, 0.f);
    float den = 0.f;
    int dp = (deg + 3) & ~3;
    int k = 0;
    for (; k + 8 <= dp; k += 8) {
        int4 a = *(const int4*)(sp + k);
        int4 b = *(const int4*)(sp + k + 4);
        int s0 = sub ? a.y : a.x;
        int s1 = sub ? a.w : a.z;
        int s2 = sub ? b.y : b.x;
        int s3 = sub ? b.w : b.z;
        float4 v0 = as4[s0];
        float4 v1 = as4[s1];
        float4 v2 = as4[s2];
        float4 v3 = as4[s3];
        float w0 = __expf(leaky(SELH(v0) + adl));
        float w1 = __expf(leaky(SELH(v1) + adl));
        float w2 = __expf(leaky(SELH(v2) + adl));
        float w3 = __expf(leaky(SELH(v3) + adl));
        float4 h0 = hp4[s0 * 16 + c];
        float4 h1 = hp4[s1 * 16 + c];
        float4 h2 = hp4[s2 * 16 + c];
        float4 h3 = hp4[s3 * 16 + c];
        m.x += w0 * h0.x + w1 * h1.x + w2 * h2.x + w3 * h3.x;
        m.y += w0 * h0.y + w1 * h1.y + w2 * h2.y + w3 * h3.y;
        m.z += w0 * h0.z + w1 * h1.z + w2 * h2.z + w3 * h3.z;
        m.w += w0 * h0.w + w1 * h1.w + w2 * h2.w + w3 * h3.w;
        den += (w0 + w1) + (w2 + w3);
    }
    if (k < dp) {   // remainder: exactly one 4-block (2 pairs)
        int4 a = *(const int4*)(sp + k);
        int s0 = sub ? a.y : a.x;
        int s1 = sub ? a.w : a.z;
        float4 v0 = as4[s0];
        float4 v1 = as4[s1];
        float w0 = __expf(leaky(SELH(v0) + adl));
        float w1 = __expf(leaky(SELH(v1) + adl));
        float4 h0 = hp4[s0 * 16 + c];
        float4 h1 = hp4[s1 * 16 + c];
        m.x += w0 * h0.x + w1 * h1.x;
        m.y += w0 * h0.y + w1 * h1.y;
        m.z += w0 * h0.z + w1 * h1.z;
        m.w += w0 * h0.w + w1 * h1.w;
        den += w0 + w1;
    }
#undef SELH

    // combine the two edge-subslots
    m.x += __shfl_xor_sync(0xffffffffu, m.x, 16);
    m.y += __shfl_xor_sync(0xffffffffu, m.y, 16);
    m.z += __shfl_xor_sync(0xffffffffu, m.z, 16);
    m.w += __shfl_xor_sync(0xffffffffu, m.w, 16);
    den += __shfl_xor_sync(0xffffffffu, den, 16);

    {   // self-loop (all lanes add identically)
        float w = __expf(leaky(g_asrc[d * 4 + hd] + adl));
        float4 hv = hp4[d * 16 + c];
        m.x += w * hv.x; m.y += w * hv.y; m.z += w * hv.z; m.w += w * hv.w;
        den += w;
    }

    float inv = 1.f / (den + 1e-16f);
    float4 r = ((const float4*)g_acc)[d * 16 + c];
    int c0 = 4 * c;
    float hb0 = fmaxf((r.x + m.x * inv) * sS[c0]     + sB[c0],     0.f);
    float hb1 = fmaxf((r.y + m.y * inv) * sS[c0 + 1] + sB[c0 + 1], 0.f);
    float hb2 = fmaxf((r.z + m.z * inv) * sS[c0 + 2] + sB[c0 + 2], 0.f);
    float hb3 = fmaxf((r.w + m.w * inv) * sS[c0 + 3] + sB[c0 + 3], 0.f);

    float lg[10];
#pragma unroll
    for (int cc = 0; cc < 10; cc++)
        lg[cc] = hb0 * sW[c0 * 10 + cc]        + hb1 * sW[(c0 + 1) * 10 + cc]
               + hb2 * sW[(c0 + 2) * 10 + cc]  + hb3 * sW[(c0 + 3) * 10 + cc];
#pragma unroll
    for (int off = 8; off; off >>= 1)
#pragma unroll
        for (int cc = 0; cc < 10; cc++)
            lg[cc] += __shfl_xor_sync(0xffffffffu, lg[cc], off);
    if (lane == 0) {
#pragma unroll
        for (int cc = 0; cc < 10; cc++) out[d * 10 + cc] = lg[cc] + sbc[cc];
    }
}

extern "C" void kernel_launch(void* const* d_in, const int* in_sizes, int n_in,
                              void* d_out, int out_size) {
    const float* x     = (const float*)d_in[0];
    const int*   ei    = (const int*)d_in[1];
    const float* Wg    = (const float*)d_in[2];
    const float* att_s = (const float*)d_in[3];
    const float* att_d = (const float*)d_in[4];
    const float* bg    = (const float*)d_in[5];
    const float* Wr    = (const float*)d_in[6];
    const float* br    = (const float*)d_in[7];
    const float* gamma = (const float*)d_in[8];
    const float* beta  = (const float*)d_in[9];
    const float* rmean = (const float*)d_in[10];
    const float* rvar  = (const float*)d_in[11];
    const float* Wc    = (const float*)d_in[12];
    const float* bc    = (const float*)d_in[13];
    float* out = (float*)d_out;

    int n = in_sizes[0] / 128;
    int E = in_sizes[1] / 2;

    int nodeB = (n + NBLK - 1) / NBLK;
    int edgeB = (E + NBLK - 1) / NBLK;
    int gemmB = (n + 31) / 32;

    static cudaStream_t s2 = nullptr;
    static cudaEvent_t evFork = nullptr, evJoin = nullptr;
    static int init_done = 0;
    if (!init_done) {
        cudaFuncSetAttribute(k_gemm, cudaFuncAttributeMaxDynamicSharedMemorySize, 81920);
        cudaStreamCreateWithFlags(&s2, cudaStreamNonBlocking);
        cudaEventCreateWithFlags(&evFork, cudaEventDisableTiming);
        cudaEventCreateWithFlags(&evJoin, cudaEventDisableTiming);
        init_done = 1;
    }

    // fork: FULL CSR build (hist + rows + scatter) overlaps with the GEMM
    cudaEventRecord(evFork, 0);
    cudaStreamWaitEvent(s2, evFork, 0);

    k_gemm<<<gemmB, NBLK, 81920>>>(x, Wg, Wr, bg, br, att_s, att_d, n);

    k_hist<<<edgeB, NBLK, 0, s2>>>(ei, E);
    k_rows<<<nodeB, NBLK, 0, s2>>>(n);
    k_scatter<<<edgeB, NBLK, 0, s2>>>(ei, E);
    cudaEventRecord(evJoin, s2);
    cudaStreamWaitEvent(0, evJoin, 0);

    k_agg<<<(n + 7) / 8, NBLK>>>(gamma, beta, rmean, rvar, Wc, bc, out, n);
}